// round 1
// baseline (speedup 1.0000x reference)
#include <cuda_runtime.h>
#include <math.h>

#define BB 16
#define NN 2048
#define MM 8192

// Scratch (allocation-free contract: __device__ globals)
__device__ unsigned g_minA_bits[BB * NN]; // per-samp-point min d2 (uint bits, atomicMin)
__device__ float    g_minB[BB * MM];      // per-ref-point min d2 (written once)

__global__ void __launch_bounds__(256) init_kernel() {
    int i = blockIdx.x * blockDim.x + threadIdx.x;
    if (i < BB * NN) g_minA_bits[i] = 0x7F800000u; // +inf
}

// Pass A: samp queries vs a 2048-point chunk of ref.
// grid = (mChunk=4, nChunk=4, b=16), block = 128 threads, 4 queries/thread.
__global__ void __launch_bounds__(128) passA_kernel(const float* __restrict__ samp,
                                                    const float* __restrict__ ref) {
    __shared__ float4 sh[2048];
    const int b  = blockIdx.z;
    const int m0 = blockIdx.x * 2048;
    const int n0 = blockIdx.y * 512;

    const float* refb = ref + (size_t)b * MM * 3;
    for (int i = threadIdx.x; i < 2048; i += 128) {
        float x = refb[(m0 + i) * 3 + 0];
        float y = refb[(m0 + i) * 3 + 1];
        float z = refb[(m0 + i) * 3 + 2];
        sh[i] = make_float4(-2.f * x, -2.f * y, -2.f * z,
                            x * x + y * y + z * z);
    }
    __syncthreads();

    const float* sampb = samp + (size_t)b * NN * 3;
    float qx[4], qy[4], qz[4], tmin[4];
    int   nidx[4];
#pragma unroll
    for (int i = 0; i < 4; i++) {
        int n = n0 + i * 128 + threadIdx.x;
        nidx[i] = n;
        qx[i] = sampb[n * 3 + 0];
        qy[i] = sampb[n * 3 + 1];
        qz[i] = sampb[n * 3 + 2];
        tmin[i] = INFINITY;
    }

#pragma unroll 4
    for (int j = 0; j < 2048; j++) {
        float4 c = sh[j];
#pragma unroll
        for (int i = 0; i < 4; i++) {
            float t = fmaf(qx[i], c.x, c.w);
            t = fmaf(qy[i], c.y, t);
            t = fmaf(qz[i], c.z, t);
            tmin[i] = fminf(tmin[i], t);
        }
    }

#pragma unroll
    for (int i = 0; i < 4; i++) {
        float s2 = qx[i] * qx[i] + qy[i] * qy[i] + qz[i] * qz[i];
        float d2 = fmaxf(s2 + tmin[i], 0.f);
        atomicMin(&g_minA_bits[b * NN + nidx[i]], __float_as_uint(d2));
    }
}

// Pass B: ref queries vs full samp DB (2048 points fits in shared).
// grid = (mChunk=16, b=16), block = 128 threads, 4 queries/thread.
__global__ void __launch_bounds__(128) passB_kernel(const float* __restrict__ samp,
                                                    const float* __restrict__ ref) {
    __shared__ float4 sh[2048];
    const int b  = blockIdx.y;
    const int m0 = blockIdx.x * 512;

    const float* sampb = samp + (size_t)b * NN * 3;
    for (int i = threadIdx.x; i < 2048; i += 128) {
        float x = sampb[i * 3 + 0];
        float y = sampb[i * 3 + 1];
        float z = sampb[i * 3 + 2];
        sh[i] = make_float4(-2.f * x, -2.f * y, -2.f * z,
                            x * x + y * y + z * z);
    }
    __syncthreads();

    const float* refb = ref + (size_t)b * MM * 3;
    float qx[4], qy[4], qz[4], tmin[4];
    int   midx[4];
#pragma unroll
    for (int i = 0; i < 4; i++) {
        int m = m0 + i * 128 + threadIdx.x;
        midx[i] = m;
        qx[i] = refb[m * 3 + 0];
        qy[i] = refb[m * 3 + 1];
        qz[i] = refb[m * 3 + 2];
        tmin[i] = INFINITY;
    }

#pragma unroll 4
    for (int j = 0; j < 2048; j++) {
        float4 c = sh[j];
#pragma unroll
        for (int i = 0; i < 4; i++) {
            float t = fmaf(qx[i], c.x, c.w);
            t = fmaf(qy[i], c.y, t);
            t = fmaf(qz[i], c.z, t);
            tmin[i] = fminf(tmin[i], t);
        }
    }

#pragma unroll
    for (int i = 0; i < 4; i++) {
        float s2 = qx[i] * qx[i] + qy[i] * qy[i] + qz[i] * qz[i];
        float d2 = fmaxf(s2 + tmin[i], 0.f);
        g_minB[b * MM + midx[i]] = d2;
    }
}

// Finalize: per-batch sums of d2 and sqrt(d2) -> cd_p, cd_t.
__global__ void __launch_bounds__(256) finalize_kernel(float* __restrict__ out) {
    const int b = blockIdx.x, tid = threadIdx.x;
    float a = 0.f, as = 0.f, c = 0.f, cs = 0.f;
    for (int i = tid; i < NN; i += 256) {
        float v = __uint_as_float(g_minA_bits[b * NN + i]);
        a += v;
        as += sqrtf(v);
    }
    for (int i = tid; i < MM; i += 256) {
        float v = g_minB[b * MM + i];
        c += v;
        cs += sqrtf(v);
    }
    __shared__ float sh[4][256];
    sh[0][tid] = a; sh[1][tid] = as; sh[2][tid] = c; sh[3][tid] = cs;
    __syncthreads();
    for (int s = 128; s > 0; s >>= 1) {
        if (tid < s) {
            sh[0][tid] += sh[0][tid + s];
            sh[1][tid] += sh[1][tid + s];
            sh[2][tid] += sh[2][tid + s];
            sh[3][tid] += sh[3][tid + s];
        }
        __syncthreads();
    }
    if (tid == 0) {
        float meanA  = sh[0][0] / (float)NN;  // mean d2, samp->ref
        float meanAs = sh[1][0] / (float)NN;  // mean sqrt
        float meanB  = sh[2][0] / (float)MM;  // mean d2, ref->samp
        float meanBs = sh[3][0] / (float)MM;
        out[b]      = 0.5f * (meanAs + meanBs); // cd_p
        out[16 + b] = meanA + meanB;            // cd_t
    }
}

extern "C" void kernel_launch(void* const* d_in, const int* in_sizes, int n_in,
                              void* d_out, int out_size) {
    // Disambiguate inputs by element count.
    const float* ref;
    const float* samp;
    if (in_sizes[0] == BB * MM * 3) {
        ref  = (const float*)d_in[0];
        samp = (const float*)d_in[1];
    } else {
        ref  = (const float*)d_in[1];
        samp = (const float*)d_in[0];
    }
    float* out = (float*)d_out;

    init_kernel<<<(BB * NN + 255) / 256, 256>>>();

    dim3 gA(4, 4, BB);          // mChunk, nChunk, batch
    passA_kernel<<<gA, 128>>>(samp, ref);

    dim3 gB(16, BB);            // mChunk, batch
    passB_kernel<<<gB, 128>>>(samp, ref);

    finalize_kernel<<<BB, 256>>>(out);
}

// round 2
// speedup vs baseline: 1.2129x; 1.2129x over previous
#include <cuda_runtime.h>
#include <math.h>

#define BB 16
#define NN 2048
#define MM 8192

// Scratch (allocation-free contract: __device__ globals)
__device__ float g_minA4[BB * 4 * NN];   // per (batch, m-chunk) minima for samp points
__device__ float g_bsums[BB * 16 * 2];   // per (batch, ref-chunk) [sum d2, sum sqrt(d2)]

// ---------- packed f32x2 helpers ----------
__device__ __forceinline__ unsigned long long pack2(float v) {
    unsigned long long r;
    asm("mov.b64 %0, {%1, %1};" : "=l"(r) : "f"(v));
    return r;
}
__device__ __forceinline__ unsigned long long ffma2(unsigned long long a,
                                                    unsigned long long b,
                                                    unsigned long long c) {
    unsigned long long d;
    asm("fma.rn.f32x2 %0, %1, %2, %3;" : "=l"(d) : "l"(a), "l"(b), "l"(c));
    return d;
}
__device__ __forceinline__ void min2(float& m, unsigned long long t) {
    float lo, hi;
    asm("mov.b64 {%0, %1}, %2;" : "=f"(lo), "=f"(hi) : "l"(t));
    m = fminf(m, fminf(lo, hi));
}

// Shared DB layout: one 32-byte record per PAIR of DB points:
// {x0,x1, y0,y1, z0,z1, w0,w1} where x' = -2x etc., w = |p|^2.
struct __align__(16) PairDB { float x0, x1, y0, y1, z0, z1, w0, w1; };

// Fused kernel.
// grid = (16, 1, 32). z<16: pass A (samp->ref), batch=z, x encodes (mchunk=x&3, nchunk=x>>2)
//                     z>=16: pass B (ref->samp), batch=z-16, x = ref chunk (512 queries)
__global__ void __launch_bounds__(128) chamfer_kernel(const float* __restrict__ samp,
                                                      const float* __restrict__ ref) {
    __shared__ PairDB sh[1024];
    __shared__ float red[2][128];

    const int z = blockIdx.z;
    const bool isA = (z < 16);
    const int b = isA ? z : z - 16;
    const int tid = threadIdx.x;

    const float* db;   // 2048 DB points
    const float* q;    // 512 query points
    int mchunk = 0;
    if (isA) {
        mchunk = blockIdx.x & 3;
        const int nchunk = blockIdx.x >> 2;
        db = ref + ((size_t)b * MM + mchunk * 2048) * 3;
        q  = samp + ((size_t)b * NN + nchunk * 512) * 3;
    } else {
        db = samp + (size_t)b * NN * 3;
        q  = ref + ((size_t)b * MM + blockIdx.x * 512) * 3;
    }

    // Fill shared DB tile (2048 points -> 1024 pair records)
    for (int i = tid; i < 2048; i += 128) {
        float x = db[i * 3 + 0];
        float y = db[i * 3 + 1];
        float zc = db[i * 3 + 2];
        float* s = &sh[i >> 1].x0 + (i & 1);
        s[0] = -2.f * x;
        s[2] = -2.f * y;
        s[4] = -2.f * zc;
        s[6] = x * x + y * y + zc * zc;
    }
    __syncthreads();

    // 4 queries per thread; duplicate each coord into both f32x2 lanes.
    float qx[4], qy[4], qz[4], tmin[4];
    unsigned long long qxd[4], qyd[4], qzd[4];
#pragma unroll
    for (int i = 0; i < 4; i++) {
        const int n = i * 128 + tid;
        qx[i] = q[n * 3 + 0];
        qy[i] = q[n * 3 + 1];
        qz[i] = q[n * 3 + 2];
        qxd[i] = pack2(qx[i]);
        qyd[i] = pack2(qy[i]);
        qzd[i] = pack2(qz[i]);
        tmin[i] = INFINITY;
    }

    const ulonglong2* __restrict__ shv = reinterpret_cast<const ulonglong2*>(sh);
#pragma unroll 2
    for (int j = 0; j < 1024; j++) {
        const ulonglong2 u = shv[2 * j];      // {x0,x1},{y0,y1}
        const ulonglong2 v = shv[2 * j + 1];  // {z0,z1},{w0,w1}
#pragma unroll
        for (int i = 0; i < 4; i++) {
            unsigned long long t = ffma2(qxd[i], u.x, v.y);
            t = ffma2(qyd[i], u.y, t);
            t = ffma2(qzd[i], v.x, t);
            min2(tmin[i], t);
        }
    }

    if (isA) {
        // Store per-(batch, mchunk) minima; final kernel combines the 4 chunks.
        const int nbase = (blockIdx.x >> 2) * 512;
#pragma unroll
        for (int i = 0; i < 4; i++) {
            float s2 = qx[i] * qx[i] + qy[i] * qy[i] + qz[i] * qz[i];
            float d2 = fmaxf(s2 + tmin[i], 0.f);
            g_minA4[((size_t)b * 4 + mchunk) * NN + nbase + i * 128 + tid] = d2;
        }
    } else {
        // Full min for these 512 ref queries: reduce sums in-block.
        float sd = 0.f, ss = 0.f;
#pragma unroll
        for (int i = 0; i < 4; i++) {
            float s2 = qx[i] * qx[i] + qy[i] * qy[i] + qz[i] * qz[i];
            float d2 = fmaxf(s2 + tmin[i], 0.f);
            sd += d2;
            ss += sqrtf(d2);
        }
        red[0][tid] = sd;
        red[1][tid] = ss;
        __syncthreads();
        for (int s = 64; s > 0; s >>= 1) {
            if (tid < s) {
                red[0][tid] += red[0][tid + s];
                red[1][tid] += red[1][tid + s];
            }
            __syncthreads();
        }
        if (tid == 0) {
            g_bsums[((size_t)b * 16 + blockIdx.x) * 2 + 0] = red[0][0];
            g_bsums[((size_t)b * 16 + blockIdx.x) * 2 + 1] = red[1][0];
        }
    }
}

// Final: combine 4 A-chunks per samp point, sqrt+sum; fold in B partial sums.
__global__ void __launch_bounds__(256) final_kernel(float* __restrict__ out) {
    const int b = blockIdx.x, tid = threadIdx.x;
    float a = 0.f, as = 0.f;
    const float* base = &g_minA4[(size_t)b * 4 * NN];
    for (int n = tid; n < NN; n += 256) {
        float v0 = base[0 * NN + n];
        float v1 = base[1 * NN + n];
        float v2 = base[2 * NN + n];
        float v3 = base[3 * NN + n];
        float v = fminf(fminf(v0, v1), fminf(v2, v3));
        a += v;
        as += sqrtf(v);
    }
    __shared__ float sh[2][256];
    sh[0][tid] = a;
    sh[1][tid] = as;
    __syncthreads();
    for (int s = 128; s > 0; s >>= 1) {
        if (tid < s) {
            sh[0][tid] += sh[0][tid + s];
            sh[1][tid] += sh[1][tid + s];
        }
        __syncthreads();
    }
    if (tid == 0) {
        float sd = 0.f, ss = 0.f;
#pragma unroll
        for (int c = 0; c < 16; c++) {
            sd += g_bsums[((size_t)b * 16 + c) * 2 + 0];
            ss += g_bsums[((size_t)b * 16 + c) * 2 + 1];
        }
        float meanA = sh[0][0] / (float)NN;
        float meanAs = sh[1][0] / (float)NN;
        float meanB = sd / (float)MM;
        float meanBs = ss / (float)MM;
        out[b] = 0.5f * (meanAs + meanBs);  // cd_p
        out[16 + b] = meanA + meanB;        // cd_t
    }
}

extern "C" void kernel_launch(void* const* d_in, const int* in_sizes, int n_in,
                              void* d_out, int out_size) {
    const float* ref;
    const float* samp;
    if (in_sizes[0] == BB * MM * 3) {
        ref = (const float*)d_in[0];
        samp = (const float*)d_in[1];
    } else {
        ref = (const float*)d_in[1];
        samp = (const float*)d_in[0];
    }
    float* out = (float*)d_out;

    dim3 grid(16, 1, 32);
    chamfer_kernel<<<grid, 128>>>(samp, ref);
    final_kernel<<<BB, 256>>>(out);
}

// round 3
// speedup vs baseline: 1.2800x; 1.0554x over previous
#include <cuda_runtime.h>
#include <math.h>

#define BB 16
#define NN 2048   // samp points (rows)
#define MM 8192   // ref points (cols)

// Scratch: partial minima (written, never read-modify — no init needed)
__device__ float g_row[4][BB][NN];     // per m-quarter: min d2 for each samp point
__device__ float g_col[16][BB][MM];    // per n-slab:    min d2 for each ref point (8MB)
__device__ float g_part[BB][9][2];     // stage-1 partial sums [piece][{sum_d2, sum_sqrt}]

// Fused kernel: each block covers 128 samp (n-slab) x 2048 ref (m-quarter).
// Every d2 is computed ONCE and feeds both the row-min and the col-min.
// grid = (mquarter=4, nslab=16, b=16), block = 256 threads (8 warps).
// Lane layout: ty = lane>>3 (4 groups), tx = lane&7 (8 groups).
// Warp w owns samp rows n_local = w*16 + ty*4 + {0..3}  (16 rows/warp, dup over tx).
// Per step: 64 ref points; lane handles m_local_in_step = tx + 8k, k=0..7.
__global__ void __launch_bounds__(256) chamfer_fused(const float* __restrict__ samp,
                                                     const float* __restrict__ ref) {
    __shared__ float4 tile[2048];       // ref points: (x, y, z, |p|^2)
    __shared__ float colpart[8][64];    // per-warp col-min partials for the step

    const int mq   = blockIdx.x;        // m quarter (2048 ref points)
    const int slab = blockIdx.y;        // n slab (128 samp points)
    const int b    = blockIdx.z;
    const int tid  = threadIdx.x;
    const int warp = tid >> 5;
    const int lane = tid & 31;
    const int ty   = lane >> 3;
    const int tx   = lane & 7;

    const int mbase = mq * 2048;

    // ---- load ref tile into shared: raw coords + squared norm ----
    const float* refb = ref + ((size_t)b * MM + mbase) * 3;
    for (int j = tid; j < 2048; j += 256) {
        float x = refb[j * 3 + 0];
        float y = refb[j * 3 + 1];
        float z = refb[j * 3 + 2];
        tile[j] = make_float4(x, y, z, x * x + y * y + z * z);
    }

    // ---- load 4 queries per lane (prescaled by -2), plus |q|^2 ----
    float qx[4], qy[4], qz[4], s2[4], rowacc[4];
    const float* sb = samp + ((size_t)b * NN + slab * 128) * 3;
#pragma unroll
    for (int i = 0; i < 4; i++) {
        const int nl = warp * 16 + ty * 4 + i;
        float x = sb[nl * 3 + 0];
        float y = sb[nl * 3 + 1];
        float z = sb[nl * 3 + 2];
        qx[i] = -2.f * x;
        qy[i] = -2.f * y;
        qz[i] = -2.f * z;
        s2[i] = x * x + y * y + z * z;
        rowacc[i] = INFINITY;
    }
    __syncthreads();

    // ---- main sweep: 32 steps of 64 ref points ----
    for (int s = 0; s < 2048; s += 64) {
        float colv[8];
#pragma unroll
        for (int k = 0; k < 8; k++) {
            const float4 p = tile[s + tx + 8 * k];
            float t0 = p.w + s2[0];
            t0 = fmaf(qx[0], p.x, t0);
            t0 = fmaf(qy[0], p.y, t0);
            t0 = fmaf(qz[0], p.z, t0);
            float t1 = p.w + s2[1];
            t1 = fmaf(qx[1], p.x, t1);
            t1 = fmaf(qy[1], p.y, t1);
            t1 = fmaf(qz[1], p.z, t1);
            float t2 = p.w + s2[2];
            t2 = fmaf(qx[2], p.x, t2);
            t2 = fmaf(qy[2], p.y, t2);
            t2 = fmaf(qz[2], p.z, t2);
            float t3 = p.w + s2[3];
            t3 = fmaf(qx[3], p.x, t3);
            t3 = fmaf(qy[3], p.y, t3);
            t3 = fmaf(qz[3], p.z, t3);
            rowacc[0] = fminf(rowacc[0], t0);
            rowacc[1] = fminf(rowacc[1], t1);
            rowacc[2] = fminf(rowacc[2], t2);
            rowacc[3] = fminf(rowacc[3], t3);
            colv[k] = fminf(fminf(t0, t1), fminf(t2, t3));
        }
        // butterfly min over the 4 ty groups (lane bits 3,4) -> min over warp's 16 rows
#pragma unroll
        for (int k = 0; k < 8; k++)
            colv[k] = fminf(colv[k], __shfl_xor_sync(0xffffffffu, colv[k], 8));
#pragma unroll
        for (int k = 0; k < 8; k++)
            colv[k] = fminf(colv[k], __shfl_xor_sync(0xffffffffu, colv[k], 16));
        if (ty == 0) {
#pragma unroll
            for (int k = 0; k < 8; k++) colpart[warp][tx + 8 * k] = colv[k];
        }
        __syncthreads();
        // reduce across the 8 warps (128 rows total) and emit block col-min
        if (tid < 64) {
            float v = colpart[0][tid];
#pragma unroll
            for (int w = 1; w < 8; w++) v = fminf(v, colpart[w][tid]);
            g_col[slab][b][mbase + s + tid] = fmaxf(v, 0.f);
        }
        __syncthreads();
    }

    // ---- finalize rows: min across the 8 tx groups, write per-quarter partial ----
#pragma unroll
    for (int i = 0; i < 4; i++) {
        rowacc[i] = fminf(rowacc[i], __shfl_xor_sync(0xffffffffu, rowacc[i], 1));
        rowacc[i] = fminf(rowacc[i], __shfl_xor_sync(0xffffffffu, rowacc[i], 2));
        rowacc[i] = fminf(rowacc[i], __shfl_xor_sync(0xffffffffu, rowacc[i], 4));
    }
    if (tx == 0) {
#pragma unroll
        for (int i = 0; i < 4; i++) {
            const int n = slab * 128 + warp * 16 + ty * 4 + i;
            g_row[mq][b][n] = fmaxf(rowacc[i], 0.f);
        }
    }
}

// Stage 1: combine partials, sqrt, partial sums.
// grid = (piece=9, b=16), block 256.
// piece 0: rows (2048 samp, combine 4 quarters).
// pieces 1..8: cols, 1024 ref each (combine 16 slabs).
__global__ void __launch_bounds__(256) final1_kernel() {
    const int piece = blockIdx.x, b = blockIdx.y, tid = threadIdx.x;
    float sd = 0.f, ss = 0.f;
    if (piece == 0) {
        for (int n = tid; n < NN; n += 256) {
            float v = fminf(fminf(g_row[0][b][n], g_row[1][b][n]),
                            fminf(g_row[2][b][n], g_row[3][b][n]));
            sd += v;
            ss += sqrtf(v);
        }
    } else {
        const int m0 = (piece - 1) * 1024;
        for (int m = m0 + tid; m < m0 + 1024; m += 256) {
            float v = g_col[0][b][m];
#pragma unroll
            for (int s = 1; s < 16; s++) v = fminf(v, g_col[s][b][m]);
            sd += v;
            ss += sqrtf(v);
        }
    }
    __shared__ float sh[2][256];
    sh[0][tid] = sd;
    sh[1][tid] = ss;
    __syncthreads();
    for (int s = 128; s > 0; s >>= 1) {
        if (tid < s) {
            sh[0][tid] += sh[0][tid + s];
            sh[1][tid] += sh[1][tid + s];
        }
        __syncthreads();
    }
    if (tid == 0) {
        g_part[b][piece][0] = sh[0][0];
        g_part[b][piece][1] = sh[1][0];
    }
}

// Stage 2: tiny combine -> outputs.
__global__ void final2_kernel(float* __restrict__ out) {
    const int b = blockIdx.x;
    if (threadIdx.x == 0) {
        float rowd = g_part[b][0][0], rows = g_part[b][0][1];
        float cold = 0.f, cols = 0.f;
#pragma unroll
        for (int p = 1; p < 9; p++) {
            cold += g_part[b][p][0];
            cols += g_part[b][p][1];
        }
        float meanA = rowd / (float)NN;   // samp->ref mean d2
        float meanAs = rows / (float)NN;  // samp->ref mean sqrt
        float meanB = cold / (float)MM;   // ref->samp mean d2
        float meanBs = cols / (float)MM;
        out[b] = 0.5f * (meanAs + meanBs);  // cd_p
        out[16 + b] = meanA + meanB;        // cd_t
    }
}

extern "C" void kernel_launch(void* const* d_in, const int* in_sizes, int n_in,
                              void* d_out, int out_size) {
    const float* ref;
    const float* samp;
    if (in_sizes[0] == BB * MM * 3) {
        ref = (const float*)d_in[0];
        samp = (const float*)d_in[1];
    } else {
        ref = (const float*)d_in[1];
        samp = (const float*)d_in[0];
    }
    float* out = (float*)d_out;

    chamfer_fused<<<dim3(4, 16, 16), 256>>>(samp, ref);
    final1_kernel<<<dim3(9, BB), 256>>>();
    final2_kernel<<<BB, 32>>>(out);
}

// round 4
// speedup vs baseline: 1.2948x; 1.0116x over previous
#include <cuda_runtime.h>
#include <math.h>

#define BB 16
#define NN 2048   // samp points (rows)
#define MM 8192   // ref points (cols)

// Scratch: partial minima (written, never read-modify — no init needed)
__device__ float g_row[4][BB][NN];     // per m-quarter: min d2 for each samp point
__device__ float g_col[16][BB][MM];    // per n-slab:    min d2 for each ref point
__device__ float g_part[BB][9][2];     // stage-1 partial sums

// Fused kernel: block covers 128 samp rows x 2048 ref cols.
// Each lane owns 8 ref cols IN REGISTERS (col-min needs no cross-lane traffic).
// Rows iterate from shared (broadcast). Row-min: in-register tree + 5-shuffle
// butterfly + per-warp smem slot; combined across warps once at block end.
// grid = (mq=4, slab=16, b=16), block = 256 (8 warps).
// Lane (w,l) owns cols mq*2048 + w*256 + l + 32*j, j=0..7.
__global__ void __launch_bounds__(256) chamfer_fused(const float* __restrict__ samp,
                                                     const float* __restrict__ ref) {
    __shared__ float4 stage[512];      // ref staging chunk (reused 4x)
    __shared__ float4 rows[128];       // samp rows: (-2x,-2y,-2z, |q|^2)
    __shared__ float  rowred[8][128];  // per-warp row minima

    const int mq   = blockIdx.x;
    const int slab = blockIdx.y;
    const int b    = blockIdx.z;
    const int tid  = threadIdx.x;
    const int w    = tid >> 5;
    const int l    = tid & 31;

    const float* refb  = ref  + ((size_t)b * MM + mq * 2048) * 3;
    const float* sampb = samp + ((size_t)b * NN + slab * 128) * 3;

    // ---- load samp rows (prescaled) ----
    if (tid < 128) {
        float x = sampb[tid * 3 + 0];
        float y = sampb[tid * 3 + 1];
        float z = sampb[tid * 3 + 2];
        rows[tid] = make_float4(-2.f * x, -2.f * y, -2.f * z, x * x + y * y + z * z);
    }

    // ---- stage ref cols in 4 chunks of 512; each lane picks up its 8 cols ----
    float cx[8], cy[8], cz[8], cw[8];
    for (int c = 0; c < 4; c++) {
        __syncthreads();
        for (int i = tid; i < 512; i += 256) {
            const float* p = refb + (c * 512 + i) * 3;
            float x = p[0], y = p[1], z = p[2];
            stage[i] = make_float4(x, y, z, x * x + y * y + z * z);
        }
        __syncthreads();
        if ((w >> 1) == c) {
            const int base = (w & 1) * 256 + l;
#pragma unroll
            for (int j = 0; j < 8; j++) {
                float4 v = stage[base + j * 32];
                cx[j] = v.x; cy[j] = v.y; cz[j] = v.z; cw[j] = v.w;
            }
        }
    }
    __syncthreads();

    float colacc[8];
#pragma unroll
    for (int j = 0; j < 8; j++) colacc[j] = INFINITY;

    // ---- mainloop: no syncs, no cross-warp traffic ----
#pragma unroll 2
    for (int r = 0; r < 128; r++) {
        const float4 q = rows[r];
        float t[8];
#pragma unroll
        for (int j = 0; j < 8; j++) {
            float v = fmaf(q.z, cz[j], cw[j]);
            v = fmaf(q.y, cy[j], v);
            v = fmaf(q.x, cx[j], v);
            t[j] = v;
            colacc[j] = fminf(colacc[j], v + q.w);  // full d2 for col side
        }
        // row-min tree over this lane's 8 cols (t excludes |q|^2, row-const)
        float rp = fminf(fminf(fminf(t[0], t[1]), fminf(t[2], t[3])),
                         fminf(fminf(t[4], t[5]), fminf(t[6], t[7])));
        rp += q.w;
        rp = fminf(rp, __shfl_xor_sync(0xffffffffu, rp, 1));
        rp = fminf(rp, __shfl_xor_sync(0xffffffffu, rp, 2));
        rp = fminf(rp, __shfl_xor_sync(0xffffffffu, rp, 4));
        rp = fminf(rp, __shfl_xor_sync(0xffffffffu, rp, 8));
        rp = fminf(rp, __shfl_xor_sync(0xffffffffu, rp, 16));
        if (l == 0) rowred[w][r] = rp;
    }

    // ---- emit col partials (complete within block over its 128 rows) ----
    {
        const int mbase = mq * 2048 + w * 256 + l;
#pragma unroll
        for (int j = 0; j < 8; j++)
            g_col[slab][b][mbase + j * 32] = fmaxf(colacc[j], 0.f);
    }

    // ---- combine row partials across the 8 warps ----
    __syncthreads();
    if (tid < 128) {
        float v = rowred[0][tid];
#pragma unroll
        for (int k = 1; k < 8; k++) v = fminf(v, rowred[k][tid]);
        g_row[mq][b][slab * 128 + tid] = fmaxf(v, 0.f);
    }
}

// Stage 1: combine partials, sqrt, partial sums. grid=(piece=9, b=16).
__global__ void __launch_bounds__(256) final1_kernel() {
    const int piece = blockIdx.x, b = blockIdx.y, tid = threadIdx.x;
    float sd = 0.f, ss = 0.f;
    if (piece == 0) {
        for (int n = tid; n < NN; n += 256) {
            float v = fminf(fminf(g_row[0][b][n], g_row[1][b][n]),
                            fminf(g_row[2][b][n], g_row[3][b][n]));
            sd += v;
            ss += sqrtf(v);
        }
    } else {
        const int m0 = (piece - 1) * 1024;
        for (int m = m0 + tid; m < m0 + 1024; m += 256) {
            float v = g_col[0][b][m];
#pragma unroll
            for (int s = 1; s < 16; s++) v = fminf(v, g_col[s][b][m]);
            sd += v;
            ss += sqrtf(v);
        }
    }
    __shared__ float sh[2][256];
    sh[0][tid] = sd;
    sh[1][tid] = ss;
    __syncthreads();
    for (int s = 128; s > 0; s >>= 1) {
        if (tid < s) {
            sh[0][tid] += sh[0][tid + s];
            sh[1][tid] += sh[1][tid + s];
        }
        __syncthreads();
    }
    if (tid == 0) {
        g_part[b][piece][0] = sh[0][0];
        g_part[b][piece][1] = sh[1][0];
    }
}

__global__ void final2_kernel(float* __restrict__ out) {
    const int b = blockIdx.x;
    if (threadIdx.x == 0) {
        float rowd = g_part[b][0][0], rows = g_part[b][0][1];
        float cold = 0.f, cols = 0.f;
#pragma unroll
        for (int p = 1; p < 9; p++) {
            cold += g_part[b][p][0];
            cols += g_part[b][p][1];
        }
        float meanA = rowd / (float)NN;
        float meanAs = rows / (float)NN;
        float meanB = cold / (float)MM;
        float meanBs = cols / (float)MM;
        out[b] = 0.5f * (meanAs + meanBs);  // cd_p
        out[16 + b] = meanA + meanB;        // cd_t
    }
}

extern "C" void kernel_launch(void* const* d_in, const int* in_sizes, int n_in,
                              void* d_out, int out_size) {
    const float* ref;
    const float* samp;
    if (in_sizes[0] == BB * MM * 3) {
        ref = (const float*)d_in[0];
        samp = (const float*)d_in[1];
    } else {
        ref = (const float*)d_in[1];
        samp = (const float*)d_in[0];
    }
    float* out = (float*)d_out;

    chamfer_fused<<<dim3(4, 16, 16), 256>>>(samp, ref);
    final1_kernel<<<dim3(9, BB), 256>>>();
    final2_kernel<<<BB, 32>>>(out);
}

// round 5
// speedup vs baseline: 1.3581x; 1.0489x over previous
#include <cuda_runtime.h>
#include <math.h>

#define BB 16
#define NN 2048   // samp points (rows)
#define MM 8192   // ref points (cols)

// Scratch: partial minima (written, never read-modify — no init needed)
__device__ float g_row[4][BB][NN];     // per m-quarter: min d2 for each samp point
__device__ float g_col[16][BB][MM];    // per n-slab:    min d2 for each ref point
__device__ float g_part[BB][9][2];     // stage-1 partial sums

typedef unsigned long long ull;

__device__ __forceinline__ ull pack2(float v) {
    ull r;
    asm("mov.b64 %0, {%1, %1};" : "=l"(r) : "f"(v));
    return r;
}
__device__ __forceinline__ ull pack_ab(float a, float b) {
    ull r;
    asm("mov.b64 %0, {%1, %2};" : "=l"(r) : "f"(a), "f"(b));
    return r;
}
__device__ __forceinline__ ull ffma2(ull a, ull b, ull c) {
    ull d;
    asm("fma.rn.f32x2 %0, %1, %2, %3;" : "=l"(d) : "l"(a), "l"(b), "l"(c));
    return d;
}
__device__ __forceinline__ ull add2(ull a, ull b) {
    ull d;
    asm("add.rn.f32x2 %0, %1, %2;" : "=l"(d) : "l"(a), "l"(b));
    return d;
}
__device__ __forceinline__ float2 unpack2(ull v) {
    float2 f;
    asm("mov.b64 {%0, %1}, %2;" : "=f"(f.x), "=f"(f.y) : "l"(v));
    return f;
}

// Fused kernel: block covers 128 samp rows x 2048 ref cols.
// Each lane owns 8 ref cols in registers, packed as 4 f32x2 pairs.
// Per row-iteration the FMA chain runs fully packed (fma.rn.f32x2);
// mins are scalar FMNMX. Row-min: tree + 5-shuffle butterfly.
// grid = (mq=4, slab=16, b=16), block = 256 (8 warps).
// Lane (w,l) owns cols mq*2048 + w*256 + l + 32*j, j=0..7; pair k packs (j=2k, j=2k+1).
__global__ void __launch_bounds__(256) chamfer_fused(const float* __restrict__ samp,
                                                     const float* __restrict__ ref) {
    __shared__ float4 stage[512];        // ref staging chunk (reused 4x)
    __shared__ ulonglong4 rowsP[128];    // samp rows, packed dup: (-2x,-2x),(-2y,-2y),(-2z,-2z),(w,w)
    __shared__ float rowred[8][128];     // per-warp row minima

    const int mq   = blockIdx.x;
    const int slab = blockIdx.y;
    const int b    = blockIdx.z;
    const int tid  = threadIdx.x;
    const int w    = tid >> 5;
    const int l    = tid & 31;

    const float* refb  = ref  + ((size_t)b * MM + mq * 2048) * 3;
    const float* sampb = samp + ((size_t)b * NN + slab * 128) * 3;

    // ---- load samp rows (prescaled, packed-duplicated) ----
    if (tid < 128) {
        float x = sampb[tid * 3 + 0];
        float y = sampb[tid * 3 + 1];
        float z = sampb[tid * 3 + 2];
        ulonglong4 r;
        r.x = pack2(-2.f * x);
        r.y = pack2(-2.f * y);
        r.z = pack2(-2.f * z);
        r.w = pack2(x * x + y * y + z * z);
        rowsP[tid] = r;
    }

    // ---- stage ref cols in 4 chunks of 512; pick up 8 cols as 4 packed pairs ----
    ull cxp[4], cyp[4], czp[4], cwp[4];
    for (int c = 0; c < 4; c++) {
        __syncthreads();
        for (int i = tid; i < 512; i += 256) {
            const float* p = refb + (c * 512 + i) * 3;
            float x = p[0], y = p[1], z = p[2];
            stage[i] = make_float4(x, y, z, x * x + y * y + z * z);
        }
        __syncthreads();
        if ((w >> 1) == c) {
            const int base = (w & 1) * 256 + l;
#pragma unroll
            for (int k = 0; k < 4; k++) {
                float4 a = stage[base + (2 * k) * 32];
                float4 d = stage[base + (2 * k + 1) * 32];
                cxp[k] = pack_ab(a.x, d.x);
                cyp[k] = pack_ab(a.y, d.y);
                czp[k] = pack_ab(a.z, d.z);
                cwp[k] = pack_ab(a.w, d.w);
            }
        }
    }
    __syncthreads();

    float colacc[8];
#pragma unroll
    for (int j = 0; j < 8; j++) colacc[j] = INFINITY;

    // ---- mainloop: packed FMA chain, no syncs ----
#pragma unroll 2
    for (int r = 0; r < 128; r++) {
        const ulonglong4 q = rowsP[r];
        float pm[4];
#pragma unroll
        for (int k = 0; k < 4; k++) {
            ull t = ffma2(q.z, czp[k], cwp[k]);
            t = ffma2(q.y, cyp[k], t);
            t = ffma2(q.x, cxp[k], t);
            ull d = add2(t, q.w);                 // full packed d2 pair
            float2 df = unpack2(d);
            colacc[2 * k]     = fminf(colacc[2 * k], df.x);
            colacc[2 * k + 1] = fminf(colacc[2 * k + 1], df.y);
            pm[k] = fminf(df.x, df.y);
        }
        float rp = fminf(fminf(pm[0], pm[1]), fminf(pm[2], pm[3]));
        rp = fminf(rp, __shfl_xor_sync(0xffffffffu, rp, 1));
        rp = fminf(rp, __shfl_xor_sync(0xffffffffu, rp, 2));
        rp = fminf(rp, __shfl_xor_sync(0xffffffffu, rp, 4));
        rp = fminf(rp, __shfl_xor_sync(0xffffffffu, rp, 8));
        rp = fminf(rp, __shfl_xor_sync(0xffffffffu, rp, 16));
        if (l == 0) rowred[w][r] = rp;
    }

    // ---- emit col partials (complete within block over its 128 rows) ----
    {
        const int mbase = mq * 2048 + w * 256 + l;
#pragma unroll
        for (int j = 0; j < 8; j++)
            g_col[slab][b][mbase + j * 32] = fmaxf(colacc[j], 0.f);
    }

    // ---- combine row partials across the 8 warps ----
    __syncthreads();
    if (tid < 128) {
        float v = rowred[0][tid];
#pragma unroll
        for (int k = 1; k < 8; k++) v = fminf(v, rowred[k][tid]);
        g_row[mq][b][slab * 128 + tid] = fmaxf(v, 0.f);
    }
}

// Stage 1: combine partials, sqrt, partial sums. grid=(piece=9, b=16).
__global__ void __launch_bounds__(256) final1_kernel() {
    const int piece = blockIdx.x, b = blockIdx.y, tid = threadIdx.x;
    float sd = 0.f, ss = 0.f;
    if (piece == 0) {
        for (int n = tid; n < NN; n += 256) {
            float v = fminf(fminf(g_row[0][b][n], g_row[1][b][n]),
                            fminf(g_row[2][b][n], g_row[3][b][n]));
            sd += v;
            ss += sqrtf(v);
        }
    } else {
        const int m0 = (piece - 1) * 1024;
        for (int m = m0 + tid; m < m0 + 1024; m += 256) {
            float v = g_col[0][b][m];
#pragma unroll
            for (int s = 1; s < 16; s++) v = fminf(v, g_col[s][b][m]);
            sd += v;
            ss += sqrtf(v);
        }
    }
    __shared__ float sh[2][256];
    sh[0][tid] = sd;
    sh[1][tid] = ss;
    __syncthreads();
    for (int s = 128; s > 0; s >>= 1) {
        if (tid < s) {
            sh[0][tid] += sh[0][tid + s];
            sh[1][tid] += sh[1][tid + s];
        }
        __syncthreads();
    }
    if (tid == 0) {
        g_part[b][piece][0] = sh[0][0];
        g_part[b][piece][1] = sh[1][0];
    }
}

__global__ void final2_kernel(float* __restrict__ out) {
    const int b = blockIdx.x;
    if (threadIdx.x == 0) {
        float rowd = g_part[b][0][0], rows = g_part[b][0][1];
        float cold = 0.f, cols = 0.f;
#pragma unroll
        for (int p = 1; p < 9; p++) {
            cold += g_part[b][p][0];
            cols += g_part[b][p][1];
        }
        float meanA = rowd / (float)NN;
        float meanAs = rows / (float)NN;
        float meanB = cold / (float)MM;
        float meanBs = cols / (float)MM;
        out[b] = 0.5f * (meanAs + meanBs);  // cd_p
        out[16 + b] = meanA + meanB;        // cd_t
    }
}

extern "C" void kernel_launch(void* const* d_in, const int* in_sizes, int n_in,
                              void* d_out, int out_size) {
    const float* ref;
    const float* samp;
    if (in_sizes[0] == BB * MM * 3) {
        ref = (const float*)d_in[0];
        samp = (const float*)d_in[1];
    } else {
        ref = (const float*)d_in[1];
        samp = (const float*)d_in[0];
    }
    float* out = (float*)d_out;

    chamfer_fused<<<dim3(4, 16, 16), 256>>>(samp, ref);
    final1_kernel<<<dim3(9, BB), 256>>>();
    final2_kernel<<<BB, 32>>>(out);
}

// round 6
// speedup vs baseline: 1.5455x; 1.1380x over previous
#include <cuda_runtime.h>
#include <math.h>

#define BB 16
#define NN 2048   // samp points (rows)
#define MM 8192   // ref points (cols)

// Scratch: partial minima (written, never read-modify — no init needed)
__device__ float g_row[4][BB][NN];     // per m-quarter: min d2 for each samp point
__device__ float g_col[16][BB][MM];    // per n-slab:    min d2 for each ref point
__device__ float g_part[BB][9][2];     // stage-1 partial sums

typedef unsigned long long ull;

__device__ __forceinline__ ull pack2(float v) {
    ull r;
    asm("mov.b64 %0, {%1, %1};" : "=l"(r) : "f"(v));
    return r;
}
__device__ __forceinline__ ull pack_ab(float a, float b) {
    ull r;
    asm("mov.b64 %0, {%1, %2};" : "=l"(r) : "f"(a), "f"(b));
    return r;
}
__device__ __forceinline__ ull ffma2(ull a, ull b, ull c) {
    ull d;
    asm("fma.rn.f32x2 %0, %1, %2, %3;" : "=l"(d) : "l"(a), "l"(b), "l"(c));
    return d;
}
__device__ __forceinline__ ull add2(ull a, ull b) {
    ull d;
    asm("add.rn.f32x2 %0, %1, %2;" : "=l"(d) : "l"(a), "l"(b));
    return d;
}
__device__ __forceinline__ float2 unpack2(ull v) {
    float2 f;
    asm("mov.b64 {%0, %1}, %2;" : "=f"(f.x), "=f"(f.y) : "l"(v));
    return f;
}

// Fused kernel: block covers 128 samp rows x 2048 ref cols.
// Each lane owns 8 ref cols in registers as 4 f32x2 pairs; packed FMA chain.
// Row-min cross-lane reduction: single redux.sync.min.u32 on clamped d2
// (valid: IEEE order == uint order for non-negative floats).
// grid = (mq=4, slab=16, b=16), block = 256 (8 warps).
__global__ void __launch_bounds__(256) chamfer_fused(const float* __restrict__ samp,
                                                     const float* __restrict__ ref) {
    __shared__ float4 stage[512];        // ref staging chunk (reused 4x)
    __shared__ ulonglong4 rowsP[128];    // samp rows packed dup: (-2x,-2x),(-2y,-2y),(-2z,-2z),(w,w)
    __shared__ float rowred[8][128];     // per-warp row minima (clamped)

    const int mq   = blockIdx.x;
    const int slab = blockIdx.y;
    const int b    = blockIdx.z;
    const int tid  = threadIdx.x;
    const int w    = tid >> 5;
    const int l    = tid & 31;

    const float* refb  = ref  + ((size_t)b * MM + mq * 2048) * 3;
    const float* sampb = samp + ((size_t)b * NN + slab * 128) * 3;

    // ---- load samp rows (prescaled, packed-duplicated) ----
    if (tid < 128) {
        float x = sampb[tid * 3 + 0];
        float y = sampb[tid * 3 + 1];
        float z = sampb[tid * 3 + 2];
        ulonglong4 r;
        r.x = pack2(-2.f * x);
        r.y = pack2(-2.f * y);
        r.z = pack2(-2.f * z);
        r.w = pack2(x * x + y * y + z * z);
        rowsP[tid] = r;
    }

    // ---- stage ref cols in 4 chunks of 512; pick up 8 cols as 4 packed pairs ----
    ull cxp[4], cyp[4], czp[4], cwp[4];
    for (int c = 0; c < 4; c++) {
        __syncthreads();
        for (int i = tid; i < 512; i += 256) {
            const float* p = refb + (c * 512 + i) * 3;
            float x = p[0], y = p[1], z = p[2];
            stage[i] = make_float4(x, y, z, x * x + y * y + z * z);
        }
        __syncthreads();
        if ((w >> 1) == c) {
            const int base = (w & 1) * 256 + l;
#pragma unroll
            for (int k = 0; k < 4; k++) {
                float4 a = stage[base + (2 * k) * 32];
                float4 d = stage[base + (2 * k + 1) * 32];
                cxp[k] = pack_ab(a.x, d.x);
                cyp[k] = pack_ab(a.y, d.y);
                czp[k] = pack_ab(a.z, d.z);
                cwp[k] = pack_ab(a.w, d.w);
            }
        }
    }
    __syncthreads();

    float colacc[8];
#pragma unroll
    for (int j = 0; j < 8; j++) colacc[j] = INFINITY;

    // ---- mainloop: packed FMA chain; 1 REDUX per row; no syncs ----
#pragma unroll 2
    for (int r = 0; r < 128; r++) {
        const ulonglong4 q = rowsP[r];
        float pm[4];
#pragma unroll
        for (int k = 0; k < 4; k++) {
            ull t = ffma2(q.z, czp[k], cwp[k]);
            t = ffma2(q.y, cyp[k], t);
            t = ffma2(q.x, cxp[k], t);
            ull d = add2(t, q.w);                 // full packed d2 pair
            float2 df = unpack2(d);
            colacc[2 * k]     = fminf(colacc[2 * k], df.x);
            colacc[2 * k + 1] = fminf(colacc[2 * k + 1], df.y);
            pm[k] = fminf(df.x, df.y);
        }
        float rp = fminf(fminf(pm[0], pm[1]), fminf(pm[2], pm[3]));
        rp = fmaxf(rp, 0.f);   // clamp so uint-order == float-order
        unsigned rm = __reduce_min_sync(0xffffffffu, __float_as_uint(rp));
        if (l == 0) rowred[w][r] = __uint_as_float(rm);
    }

    // ---- emit col partials (complete within block over its 128 rows) ----
    {
        const int mbase = mq * 2048 + w * 256 + l;
#pragma unroll
        for (int j = 0; j < 8; j++)
            g_col[slab][b][mbase + j * 32] = fmaxf(colacc[j], 0.f);
    }

    // ---- combine row partials across the 8 warps ----
    __syncthreads();
    if (tid < 128) {
        float v = rowred[0][tid];
#pragma unroll
        for (int k = 1; k < 8; k++) v = fminf(v, rowred[k][tid]);
        g_row[mq][b][slab * 128 + tid] = v;   // already clamped
    }
}

// Stage 1: combine partials, sqrt, partial sums. grid=(piece=9, b=16).
__global__ void __launch_bounds__(256) final1_kernel() {
    const int piece = blockIdx.x, b = blockIdx.y, tid = threadIdx.x;
    float sd = 0.f, ss = 0.f;
    if (piece == 0) {
        for (int n = tid; n < NN; n += 256) {
            float v = fminf(fminf(g_row[0][b][n], g_row[1][b][n]),
                            fminf(g_row[2][b][n], g_row[3][b][n]));
            sd += v;
            ss += sqrtf(v);
        }
    } else {
        const int m0 = (piece - 1) * 1024;
        for (int m = m0 + tid; m < m0 + 1024; m += 256) {
            float v = g_col[0][b][m];
#pragma unroll
            for (int s = 1; s < 16; s++) v = fminf(v, g_col[s][b][m]);
            sd += v;
            ss += sqrtf(v);
        }
    }
    __shared__ float sh[2][256];
    sh[0][tid] = sd;
    sh[1][tid] = ss;
    __syncthreads();
    for (int s = 128; s > 0; s >>= 1) {
        if (tid < s) {
            sh[0][tid] += sh[0][tid + s];
            sh[1][tid] += sh[1][tid + s];
        }
        __syncthreads();
    }
    if (tid == 0) {
        g_part[b][piece][0] = sh[0][0];
        g_part[b][piece][1] = sh[1][0];
    }
}

__global__ void final2_kernel(float* __restrict__ out) {
    const int b = blockIdx.x;
    if (threadIdx.x == 0) {
        float rowd = g_part[b][0][0], rows = g_part[b][0][1];
        float cold = 0.f, cols = 0.f;
#pragma unroll
        for (int p = 1; p < 9; p++) {
            cold += g_part[b][p][0];
            cols += g_part[b][p][1];
        }
        float meanA = rowd / (float)NN;
        float meanAs = rows / (float)NN;
        float meanB = cold / (float)MM;
        float meanBs = cols / (float)MM;
        out[b] = 0.5f * (meanAs + meanBs);  // cd_p
        out[16 + b] = meanA + meanB;        // cd_t
    }
}

extern "C" void kernel_launch(void* const* d_in, const int* in_sizes, int n_in,
                              void* d_out, int out_size) {
    const float* ref;
    const float* samp;
    if (in_sizes[0] == BB * MM * 3) {
        ref = (const float*)d_in[0];
        samp = (const float*)d_in[1];
    } else {
        ref = (const float*)d_in[1];
        samp = (const float*)d_in[0];
    }
    float* out = (float*)d_out;

    chamfer_fused<<<dim3(4, 16, 16), 256>>>(samp, ref);
    final1_kernel<<<dim3(9, BB), 256>>>();
    final2_kernel<<<BB, 32>>>(out);
}